// round 14
// baseline (speedup 1.0000x reference)
#include <cuda_runtime.h>
#include <cuda_bf16.h>
#include <math.h>

// ---------------------------------------------------------------------------
// Problem constants
// ---------------------------------------------------------------------------
#define BATCH 4
#define HP 22
#define WP 22
#define NK 9            // anchors per cell
#define NANCH (NK*HP*WP) // 4356
#define NR 256          // rois per batch
#define NG 4            // gt boxes per batch
#define RX 28
#define RY 28
#define FEATC 128

// output layout (flattened tuple, float32)
#define OFF_FEATS   0
#define SZ_FEATS    (BATCH*FEATC*HP*WP)              // 247808
#define OFF_CONF    (OFF_FEATS + SZ_FEATS)           // 247808
#define SZ_CONF     (BATCH*NK*HP*WP)                 // 17424
#define OFF_DIFFS   (OFF_CONF + SZ_CONF)             // 265232
#define SZ_DIFFS    (BATCH*4*NK*HP*WP)               // 69696
#define OFF_REG     (OFF_DIFFS + SZ_DIFFS)           // 334928
#define SZ_REG      ((size_t)BATCH*NR*FEATC*RX*RY)   // 102760448
#define OFF_IOUMAX  (OFF_REG + SZ_REG)               // 103095376
#define SZ_IOUMAX   (BATCH*NANCH)                    // 17424
#define OFF_IOUARG  (OFF_IOUMAX + SZ_IOUMAX)         // 103112800

// ---------------------------------------------------------------------------
// Scratch (no allocations allowed -> device globals)
// ---------------------------------------------------------------------------
__device__ float g_buf0[4*16*110*110];   // 774400
__device__ float g_buf1[4*16*110*110];   // 774400
__device__ float g_buf2[4*256*22*22];    // 495616

// ---------------------------------------------------------------------------
// 3x3 conv + bias (+relu), NCHW, OIHW weights.
// ---------------------------------------------------------------------------
template<int BT, int PAD, bool RELU, int OCB>
__global__ void conv3x3_kernel(const float* __restrict__ in,
                               const float* __restrict__ wgt,
                               const float* __restrict__ bias,
                               float* __restrict__ out,
                               int IC, int OC, int Hin, int Win,
                               int Hout, int Wout)
{
    constexpr int TS = 2 * BT;      // output macro tile
    constexpr int IT = TS + 2;      // input tile (3x3, stride 1)
    constexpr int NT = BT * BT;
    __shared__ float tile[IT][IT + 1];
    __shared__ float wsh[OCB][9];

    const int groups = (OC + OCB - 1) / OCB;
    const int b   = blockIdx.z / groups;
    const int oc0 = (blockIdx.z % groups) * OCB;
    const int ty0 = blockIdx.y * TS;
    const int tx0 = blockIdx.x * TS;
    const int lx = threadIdx.x, ly = threadIdx.y;
    const int tid = ly * BT + lx;

    float acc[OCB][2][2];
#pragma unroll
    for (int j = 0; j < OCB; j++)
#pragma unroll
        for (int py = 0; py < 2; py++)
#pragma unroll
            for (int px = 0; px < 2; px++) acc[j][py][px] = 0.f;

    for (int ic = 0; ic < IC; ic++) {
        const float* ip = in + ((size_t)(b * IC + ic)) * Hin * Win;
        for (int i = tid; i < IT * IT; i += NT) {
            int rr = i / IT, cc = i % IT;
            int gy = ty0 - PAD + rr, gx = tx0 - PAD + cc;
            float v = 0.f;
            if (gy >= 0 && gy < Hin && gx >= 0 && gx < Win)
                v = ip[gy * Win + gx];
            tile[rr][cc] = v;
        }
        if (tid < OCB * 9) {
            int j = tid / 9, t = tid % 9;
            wsh[j][t] = (oc0 + j < OC) ? wgt[((size_t)(oc0 + j) * IC + ic) * 9 + t] : 0.f;
        }
        __syncthreads();

        float rin[4][4];
#pragma unroll
        for (int dy = 0; dy < 4; dy++)
#pragma unroll
            for (int dx = 0; dx < 4; dx++)
                rin[dy][dx] = tile[2 * ly + dy][2 * lx + dx];

#pragma unroll
        for (int j = 0; j < OCB; j++) {
#pragma unroll
            for (int ky = 0; ky < 3; ky++)
#pragma unroll
                for (int kx = 0; kx < 3; kx++) {
                    float wv = wsh[j][ky * 3 + kx];
                    acc[j][0][0] += rin[ky + 0][kx + 0] * wv;
                    acc[j][0][1] += rin[ky + 0][kx + 1] * wv;
                    acc[j][1][0] += rin[ky + 1][kx + 0] * wv;
                    acc[j][1][1] += rin[ky + 1][kx + 1] * wv;
                }
        }
        __syncthreads();
    }

#pragma unroll
    for (int j = 0; j < OCB; j++) {
        int oc = oc0 + j;
        if (oc >= OC) continue;
        float bv = bias[oc];
#pragma unroll
        for (int py = 0; py < 2; py++) {
            int oy = ty0 + 2 * ly + py;
            if (oy >= Hout) continue;
#pragma unroll
            for (int px = 0; px < 2; px++) {
                int ox = tx0 + 2 * lx + px;
                if (ox >= Wout) continue;
                float v = acc[j][py][px] + bv;
                if (RELU) v = fmaxf(v, 0.f);
                out[((size_t)(b * OC + oc) * Hout + oy) * Wout + ox] = v;
            }
        }
    }
}

// ---------------------------------------------------------------------------
// 2x2 maxpool, stride 2, VALID
// ---------------------------------------------------------------------------
__global__ void maxpool_kernel(const float* __restrict__ in, float* __restrict__ out,
                               int Hin, int Win, int Hout, int Wout, int n)
{
    int idx = blockIdx.x * blockDim.x + threadIdx.x;
    if (idx >= n) return;
    int ox = idx % Wout;
    int oy = (idx / Wout) % Hout;
    int bc = idx / (Wout * Hout);
    const float* p = in + ((size_t)bc * Hin + 2 * oy) * Win + 2 * ox;
    out[idx] = fmaxf(fmaxf(p[0], p[1]), fmaxf(p[Win], p[Win + 1]));
}

// ---------------------------------------------------------------------------
// 1x1 head conv (45 ch) fused with sigmoid(ch0..8)->conf and ch9..44->diffs
// ---------------------------------------------------------------------------
__global__ void head1x1_kernel(const float* __restrict__ r0,
                               const float* __restrict__ w,
                               const float* __restrict__ bias,
                               float* __restrict__ conf,
                               float* __restrict__ diffs)
{
    const int P = HP * WP;                 // 484
    int idx = blockIdx.x * blockDim.x + threadIdx.x;
    int total = BATCH * 45 * P;
    if (idx >= total) return;
    int p = idx % P;
    int c = (idx / P) % 45;
    int b = idx / (P * 45);
    float acc = bias[c];
    const float* rp = r0 + (size_t)b * 256 * P + p;
    const float* wp = w + c * 256;
#pragma unroll 8
    for (int ic = 0; ic < 256; ic++)
        acc += rp[(size_t)ic * P] * wp[ic];
    if (c < 9) {
        conf[((size_t)b * 9 + c) * P + p] = 1.0f / (1.0f + expf(-acc));
    } else {
        diffs[((size_t)b * 36 + (c - 9)) * P + p] = acc;
    }
}

// ---------------------------------------------------------------------------
// ROI bilinear crop (crop_one). grid=(chan_chunks, NR, BATCH), 256 thr.
// ---------------------------------------------------------------------------
__global__ void regions_kernel(const float* __restrict__ feats,
                               const int* __restrict__ boxes,
                               float* __restrict__ out)
{
    const int CCH = 32;                    // channels per block
    int b = blockIdx.z;
    int r = blockIdx.y;
    int c0 = blockIdx.x * CCH;
    __shared__ int   sx0[RY], sx1[RY], sy0[RX], sy1[RX];
    __shared__ float sfx[RY], sfy[RX];
    int tid = threadIdx.x;

    if (tid < 56) {
        int axis = tid / 28;               // 0 -> y (box comps 0,2), 1 -> x (1,3)
        int i = tid % 28;
        int lo = boxes[((size_t)b * 4 + (axis == 0 ? 0 : 1)) * NR + r];
        int hi = boxes[((size_t)b * 4 + (axis == 0 ? 2 : 3)) * NR + r];
        float L = (float)(hi - lo + 1);
        float g = __fsub_rn(__fdiv_rn(__fmul_rn((float)i + 0.5f, L), 28.0f), 0.5f);
        g = __fadd_rn(fminf(fmaxf(g, 0.0f), __fsub_rn(L, 1.0f)), (float)lo);
        int i0 = (int)floorf(g);
        float f = __fsub_rn(g, (float)i0);  // f computed BEFORE clamp (matches ref)
        i0 = min(i0, hi);
        int i1 = min(i0 + 1, hi);
        if (axis == 0) { sy0[i] = i0; sy1[i] = i1; sfy[i] = f; }
        else           { sx0[i] = i0; sx1[i] = i1; sfx[i] = f; }
    }
    __syncthreads();

    const float* fb = feats + (size_t)b * FEATC * HP * WP;
    float* ob = out + (((size_t)(b * NR + r) * FEATC + c0)) * (RX * RY);
    const int NE = CCH * RX * RY;          // 25088
    for (int e = tid; e < NE; e += blockDim.x) {
        int c = e / (RX * RY);
        int p = e % (RX * RY);
        int oy = p / RY, ox = p % RY;
        const float* fc = fb + (size_t)(c0 + c) * HP * WP;
        int y0 = sy0[oy], y1 = sy1[oy], x0 = sx0[ox], x1 = sx1[ox];
        float fy = sfy[oy], fx = sfx[ox];
        float r0v = fc[y0 * WP + x0] * (1.0f - fy) + fc[y1 * WP + x0] * fy;
        float r1v = fc[y0 * WP + x1] * (1.0f - fy) + fc[y1 * WP + x1] * fy;
        ob[e] = r0v * (1.0f - fx) + r1v * fx;
    }
}

// ---------------------------------------------------------------------------
// IoU max / argmax vs 4356 anchors, with .at[g,best_g].max(0.6) update.
//
// KEY CHANGE (under test since R12): XLA:GPU lowers f32 `divide` to PTX
// div.full.f32 — a full-range APPROXIMATE division (~2 ulp), not div.rn.
// This is the only non-correctly-rounded op in the reference's eager chain,
// and the 2-ulp class perturbation my FMA probes (all winner-neutral at
// <=1/2 ulp) could never reach. Both divisions in the decisive chain use it:
//   - anchor centers (i+0.5)/22  (perturbs a_an plateau structure)
//   - the iou quotient            (can tie/reorder near-equal quotients)
// Everything else: separately-rounded RN f32 (eager op-per-op, no FMA).
// argmax: FIRST occurrence (only tie-break consistent with evidence).
// ---------------------------------------------------------------------------
__device__ __forceinline__ float fdiv_full(float a, float b)
{
    float r;
    asm("div.full.f32 %0, %1, %2;" : "=f"(r) : "f"(a), "f"(b));
    return r;
}

__device__ __forceinline__ void anchor_coords(int a, const float* wh, const float* hh,
                                              float& ax1, float& ay1, float& ax2, float& ay2)
{
    int k = a / (HP * WP);
    int rem = a % (HP * WP);
    int iy = rem / WP, ix = rem % WP;
    float cx = fdiv_full((float)ix + 0.5f, (float)WP);
    float cy = fdiv_full((float)iy + 0.5f, (float)HP);
    ax1 = __fsub_rn(cx, wh[k]); ay1 = __fsub_rn(cy, hh[k]);
    ax2 = __fadd_rn(cx, wh[k]); ay2 = __fadd_rn(cy, hh[k]);
}

__device__ __forceinline__ float iou_one(float gx1, float gy1, float gx2, float gy2,
                                         float ax1, float ay1, float ax2, float ay2,
                                         float a_an)
{
    float ix1 = fmaxf(gx1, ax1), iy1 = fmaxf(gy1, ay1);
    float ix2 = fminf(gx2, ax2), iy2 = fminf(gy2, ay2);
    float cxw = fmaxf(__fsub_rn(ix2, ix1), 0.f);
    float cyw = fmaxf(__fsub_rn(iy2, iy1), 0.f);
    float inter = __fmul_rn(cxw, cyw);
    float a_gt = __fmul_rn(__fsub_rn(gx2, gx1), __fsub_rn(gy2, gy1));
    float denom = __fadd_rn(__fsub_rn(__fadd_rn(a_gt, a_an), inter), 1e-9f);
    return fdiv_full(inter, denom);
}

__global__ void iou_kernel(const float* __restrict__ gt_boxes,
                           float* __restrict__ iou_max_out,
                           float* __restrict__ iou_arg_out)
{
    int b = blockIdx.x;
    int tid = threadIdx.x;
    __shared__ float sgt[16];
    __shared__ float s_wh[NK], s_hh[NK];
    __shared__ float redv[256];
    __shared__ int   redi[256];
    __shared__ int   bestA[NG];

    if (tid < 16) sgt[tid] = gt_boxes[b * 16 + tid];
    if (tid < NK) {
        const double S[3] = {0.15, 0.45, 0.75};
        const double R[3] = {0.5, 1.0, 2.0};
        int si = tid / 3, ri = tid % 3;
        s_wh[tid] = (float)(S[si] * sqrt(R[ri]) * 0.5);
        s_hh[tid] = (float)(S[si] / sqrt(R[ri]) * 0.5);
    }
    __syncthreads();

    // phase 1: per-gt argmax over anchors (FIRST occurrence on ties)
    float bv[NG]; int bi[NG];
#pragma unroll
    for (int g = 0; g < NG; g++) { bv[g] = -1.0f; bi[g] = 0; }

    for (int a = tid; a < NANCH; a += 256) {
        float ax1, ay1, ax2, ay2;
        anchor_coords(a, s_wh, s_hh, ax1, ay1, ax2, ay2);
        float a_an = __fmul_rn(__fsub_rn(ax2, ax1), __fsub_rn(ay2, ay1));
#pragma unroll
        for (int g = 0; g < NG; g++) {
            float v = iou_one(sgt[g], sgt[4 + g], sgt[8 + g], sgt[12 + g],
                              ax1, ay1, ax2, ay2, a_an);
            if (v > bv[g]) { bv[g] = v; bi[g] = a; }   // strict > keeps FIRST
        }
    }
    for (int g = 0; g < NG; g++) {
        redv[tid] = bv[g]; redi[tid] = bi[g];
        __syncthreads();
        for (int s = 128; s > 0; s >>= 1) {
            if (tid < s) {
                float v2 = redv[tid + s]; int i2 = redi[tid + s];
                if (v2 > redv[tid] || (v2 == redv[tid] && i2 < redi[tid])) {
                    redv[tid] = v2; redi[tid] = i2;     // min index on ties
                }
            }
            __syncthreads();
        }
        if (tid == 0) bestA[g] = redi[0];
        __syncthreads();
    }

    // phase 2: per-anchor max/argmax over gts with the 0.6 scatter applied
    for (int a = tid; a < NANCH; a += 256) {
        float ax1, ay1, ax2, ay2;
        anchor_coords(a, s_wh, s_hh, ax1, ay1, ax2, ay2);
        float a_an = __fmul_rn(__fsub_rn(ax2, ax1), __fsub_rn(ay2, ay1));
        float m = -1.0f; int am = 0;
#pragma unroll
        for (int g = 0; g < NG; g++) {
            float v = iou_one(sgt[g], sgt[4 + g], sgt[8 + g], sgt[12 + g],
                              ax1, ay1, ax2, ay2, a_an);
            if (a == bestA[g]) v = fmaxf(v, 0.6f);
            if (v > m) { m = v; am = g; }               // strict > keeps FIRST
        }
        iou_max_out[b * NANCH + a] = m;
        iou_arg_out[b * NANCH + a] = (float)am;
    }
}

// ---------------------------------------------------------------------------
// Launch
// ---------------------------------------------------------------------------
static inline int cdiv(int a, int b) { return (a + b - 1) / b; }

extern "C" void kernel_launch(void* const* d_in, const int* in_sizes, int n_in,
                              void* d_out, int out_size)
{
    const float* x     = (const float*)d_in[0];
    const int*   boxes = (const int*)  d_in[1];
    const float* gt    = (const float*)d_in[2];
    const float* fw[8]; const float* fb[8];
    for (int i = 0; i < 8; i++) {
        fw[i] = (const float*)d_in[3 + 2 * i];
        fb[i] = (const float*)d_in[4 + 2 * i];
    }
    const float* rw0 = (const float*)d_in[19];
    const float* rb0 = (const float*)d_in[20];
    const float* rw1 = (const float*)d_in[21];
    const float* rb1 = (const float*)d_in[22];
    float* out = (float*)d_out;

    float *b0, *b1, *b2;
    cudaGetSymbolAddress((void**)&b0, g_buf0);
    cudaGetSymbolAddress((void**)&b1, g_buf1);
    cudaGetSymbolAddress((void**)&b2, g_buf2);

    float* feats = out + OFF_FEATS;
    float* conf  = out + OFF_CONF;
    float* diffs = out + OFF_DIFFS;
    float* reg   = out + OFF_REG;
    float* ioumx = out + OFF_IOUMAX;
    float* iouag = out + OFF_IOUARG;

    dim3 t16(16, 16), t12(12, 12);

    // conv0: 1->16, 112->110, pad0
    conv3x3_kernel<16, 0, true, 8><<<dim3(cdiv(110, 32), cdiv(110, 32), BATCH * 2), t16>>>(
        x, fw[0], fb[0], b0, 1, 16, 112, 112, 110, 110);
    // conv1: 16->16, 110, pad1
    conv3x3_kernel<16, 1, true, 8><<<dim3(cdiv(110, 32), cdiv(110, 32), BATCH * 2), t16>>>(
        b0, fw[1], fb[1], b1, 16, 16, 110, 110, 110, 110);
    // pool1: 110->55
    {
        int n = BATCH * 16 * 55 * 55;
        maxpool_kernel<<<cdiv(n, 256), 256>>>(b1, b2, 110, 110, 55, 55, n);
    }
    // conv2: 16->32, 55->53, pad0
    conv3x3_kernel<16, 0, true, 4><<<dim3(cdiv(53, 32), cdiv(53, 32), BATCH * 8), t16>>>(
        b2, fw[2], fb[2], b0, 16, 32, 55, 55, 53, 53);
    // conv3: 32->32, 53, pad1
    conv3x3_kernel<16, 1, true, 4><<<dim3(cdiv(53, 32), cdiv(53, 32), BATCH * 8), t16>>>(
        b0, fw[3], fb[3], b1, 32, 32, 53, 53, 53, 53);
    // pool2: 53->26
    {
        int n = BATCH * 32 * 26 * 26;
        maxpool_kernel<<<cdiv(n, 256), 256>>>(b1, b2, 53, 53, 26, 26, n);
    }
    // conv4: 32->64, 26->24, pad0
    conv3x3_kernel<12, 0, true, 4><<<dim3(1, 1, BATCH * 16), t12>>>(
        b2, fw[4], fb[4], b0, 32, 64, 26, 26, 24, 24);
    // conv5: 64->64, 24, pad1
    conv3x3_kernel<12, 1, true, 4><<<dim3(1, 1, BATCH * 16), t12>>>(
        b0, fw[5], fb[5], b1, 64, 64, 24, 24, 24, 24);
    // conv6: 64->128, 24->22, pad0
    conv3x3_kernel<12, 0, true, 4><<<dim3(1, 1, BATCH * 32), t12>>>(
        b1, fw[6], fb[6], b0, 64, 128, 24, 24, 22, 22);
    // conv7: 128->128, 22, pad1 -> feats (straight into output)
    conv3x3_kernel<12, 1, true, 4><<<dim3(1, 1, BATCH * 32), t12>>>(
        b0, fw[7], fb[7], feats, 128, 128, 22, 22, 22, 22);
    // rw0: 128->256, 22, pad1, relu
    conv3x3_kernel<12, 1, true, 8><<<dim3(1, 1, BATCH * 32), t12>>>(
        feats, rw0, rb0, b2, 128, 256, 22, 22, 22, 22);
    // rw1 1x1 head -> conf + diffs (fused sigmoid/split)
    {
        int total = BATCH * 45 * HP * WP;
        head1x1_kernel<<<cdiv(total, 256), 256>>>(b2, rw1, rb1, conf, diffs);
    }
    // regions: bilinear crops
    regions_kernel<<<dim3(FEATC / 32, NR, BATCH), 256>>>(feats, boxes, reg);
    // iou
    iou_kernel<<<BATCH, 256>>>(gt, ioumx, iouag);
}

// round 15
// speedup vs baseline: 2.2935x; 2.2935x over previous
#include <cuda_runtime.h>
#include <cuda_bf16.h>
#include <math.h>

// ---------------------------------------------------------------------------
// Problem constants
// ---------------------------------------------------------------------------
#define BATCH 4
#define HP 22
#define WP 22
#define NK 9            // anchors per cell
#define NANCH (NK*HP*WP) // 4356
#define NR 256          // rois per batch
#define NG 4            // gt boxes per batch
#define RX 28
#define RY 28
#define FEATC 128

// output layout (flattened tuple, float32)
#define OFF_FEATS   0
#define SZ_FEATS    (BATCH*FEATC*HP*WP)              // 247808
#define OFF_CONF    (OFF_FEATS + SZ_FEATS)           // 247808
#define SZ_CONF     (BATCH*NK*HP*WP)                 // 17424
#define OFF_DIFFS   (OFF_CONF + SZ_CONF)             // 265232
#define SZ_DIFFS    (BATCH*4*NK*HP*WP)               // 69696
#define OFF_REG     (OFF_DIFFS + SZ_DIFFS)           // 334928
#define SZ_REG      ((size_t)BATCH*NR*FEATC*RX*RY)   // 102760448
#define OFF_IOUMAX  (OFF_REG + SZ_REG)               // 103095376
#define SZ_IOUMAX   (BATCH*NANCH)                    // 17424
#define OFF_IOUARG  (OFF_IOUMAX + SZ_IOUMAX)         // 103112800

// ---------------------------------------------------------------------------
// Scratch (no allocations allowed -> device globals)
// ---------------------------------------------------------------------------
__device__ float g_buf0[4*16*110*110];   // 774400
__device__ float g_buf1[4*16*110*110];   // 774400
__device__ float g_buf2[4*256*22*22];    // 495616

// ---------------------------------------------------------------------------
// conv3x3 v2: 3x3 conv + bias + relu, NCHW, OIHW.
// Block = 256 threads (1D). grid = (spatial_tiles, oc_groups, batch).
// Stages ICB input-channel tiles per __syncthreads pair; each thread owns
// PIX pixels x OCB output channels in registers.
// ---------------------------------------------------------------------------
template<int TH, int TW, int OCB, int ICB, int PIX, int PAD, bool RELU>
__global__ __launch_bounds__(256) void conv3x3_v2(
    const float* __restrict__ in,
    const float* __restrict__ wgt,
    const float* __restrict__ bias,
    float* __restrict__ out,
    int IC, int OC, int Hin, int Win, int Hout, int Wout)
{
    constexpr int ITH = TH + 2, ITW = TW + 2;
    constexpr int NT = 256;
    __shared__ float s_in[ICB][ITH][ITW];
    __shared__ float s_w[OCB][ICB][9];

    const int tiles_x = (Wout + TW - 1) / TW;
    const int tile = blockIdx.x;
    const int tx0 = (tile % tiles_x) * TW;
    const int ty0 = (tile / tiles_x) * TH;
    const int oc0 = blockIdx.y * OCB;
    const int b = blockIdx.z;
    const int tid = threadIdx.x;

    float acc[PIX][OCB];
#pragma unroll
    for (int p = 0; p < PIX; p++)
#pragma unroll
        for (int j = 0; j < OCB; j++) acc[p][j] = 0.f;

    for (int ic0 = 0; ic0 < IC; ic0 += ICB) {
        // stage ICB input channel tiles
        constexpr int LD = ICB * ITH * ITW;
        for (int i = tid; i < LD; i += NT) {
            int c = i / (ITH * ITW);
            int rem = i % (ITH * ITW);
            int r = rem / ITW, cc = rem % ITW;
            int gy = ty0 - PAD + r, gx = tx0 - PAD + cc;
            float v = 0.f;
            if (gy >= 0 && gy < Hin && gx >= 0 && gx < Win)
                v = in[((size_t)(b * IC + (ic0 + c)) * Hin + gy) * Win + gx];
            s_in[c][r][cc] = v;
        }
        // stage weights
        for (int i = tid; i < OCB * ICB * 9; i += NT) {
            int j = i / (ICB * 9);
            int rem = i % (ICB * 9);
            int c = rem / 9, t = rem % 9;
            s_w[j][c][t] = wgt[((size_t)(oc0 + j) * IC + (ic0 + c)) * 9 + t];
        }
        __syncthreads();

#pragma unroll
        for (int p = 0; p < PIX; p++) {
            int pix = tid + p * NT;
            if (pix < TH * TW) {
                int py = pix / TW, px = pix % TW;
#pragma unroll
                for (int c = 0; c < ICB; c++) {
                    float w00 = s_in[c][py + 0][px + 0];
                    float w01 = s_in[c][py + 0][px + 1];
                    float w02 = s_in[c][py + 0][px + 2];
                    float w10 = s_in[c][py + 1][px + 0];
                    float w11 = s_in[c][py + 1][px + 1];
                    float w12 = s_in[c][py + 1][px + 2];
                    float w20 = s_in[c][py + 2][px + 0];
                    float w21 = s_in[c][py + 2][px + 1];
                    float w22 = s_in[c][py + 2][px + 2];
#pragma unroll
                    for (int j = 0; j < OCB; j++) {
                        float s = acc[p][j];
                        s += w00 * s_w[j][c][0];
                        s += w01 * s_w[j][c][1];
                        s += w02 * s_w[j][c][2];
                        s += w10 * s_w[j][c][3];
                        s += w11 * s_w[j][c][4];
                        s += w12 * s_w[j][c][5];
                        s += w20 * s_w[j][c][6];
                        s += w21 * s_w[j][c][7];
                        s += w22 * s_w[j][c][8];
                        acc[p][j] = s;
                    }
                }
            }
        }
        __syncthreads();
    }

#pragma unroll
    for (int p = 0; p < PIX; p++) {
        int pix = tid + p * NT;
        if (pix < TH * TW) {
            int oy = ty0 + pix / TW, ox = tx0 + pix % TW;
            if (oy < Hout && ox < Wout) {
#pragma unroll
                for (int j = 0; j < OCB; j++) {
                    float v = acc[p][j] + bias[oc0 + j];
                    if (RELU) v = fmaxf(v, 0.f);
                    out[((size_t)(b * OC + oc0 + j) * Hout + oy) * Wout + ox] = v;
                }
            }
        }
    }
}

// ---------------------------------------------------------------------------
// 2x2 maxpool, stride 2, VALID
// ---------------------------------------------------------------------------
__global__ void maxpool_kernel(const float* __restrict__ in, float* __restrict__ out,
                               int Hin, int Win, int Hout, int Wout, int n)
{
    int idx = blockIdx.x * blockDim.x + threadIdx.x;
    if (idx >= n) return;
    int ox = idx % Wout;
    int oy = (idx / Wout) % Hout;
    int bc = idx / (Wout * Hout);
    const float* p = in + ((size_t)bc * Hin + 2 * oy) * Win + 2 * ox;
    out[idx] = fmaxf(fmaxf(p[0], p[1]), fmaxf(p[Win], p[Win + 1]));
}

// ---------------------------------------------------------------------------
// 1x1 head conv (45 ch) fused with sigmoid(ch0..8)->conf and ch9..44->diffs
// ---------------------------------------------------------------------------
__global__ void head1x1_kernel(const float* __restrict__ r0,
                               const float* __restrict__ w,
                               const float* __restrict__ bias,
                               float* __restrict__ conf,
                               float* __restrict__ diffs)
{
    const int P = HP * WP;                 // 484
    int idx = blockIdx.x * blockDim.x + threadIdx.x;
    int total = BATCH * 45 * P;
    if (idx >= total) return;
    int p = idx % P;
    int c = (idx / P) % 45;
    int b = idx / (P * 45);
    float acc = bias[c];
    const float* rp = r0 + (size_t)b * 256 * P + p;
    const float* wp = w + c * 256;
#pragma unroll 8
    for (int ic = 0; ic < 256; ic++)
        acc += rp[(size_t)ic * P] * wp[ic];
    if (c < 9) {
        conf[((size_t)b * 9 + c) * P + p] = 1.0f / (1.0f + expf(-acc));
    } else {
        diffs[((size_t)b * 36 + (c - 9)) * P + p] = acc;
    }
}

// ---------------------------------------------------------------------------
// ROI bilinear crop (crop_one). grid=(chan_chunks, NR, BATCH), 256 thr.
// coords setup identical to the passing kernel; body float4-vectorized
// (28 % 4 == 0, rows never split; per-element arithmetic unchanged).
// ---------------------------------------------------------------------------
__global__ void regions_kernel(const float* __restrict__ feats,
                               const int* __restrict__ boxes,
                               float* __restrict__ out)
{
    const int CCH = 32;                    // channels per block
    int b = blockIdx.z;
    int r = blockIdx.y;
    int c0 = blockIdx.x * CCH;
    __shared__ int   sx0[RY], sx1[RY], sy0[RX], sy1[RX];
    __shared__ float sfx[RY], sfy[RX];
    int tid = threadIdx.x;

    if (tid < 56) {
        int axis = tid / 28;               // 0 -> y (box comps 0,2), 1 -> x (1,3)
        int i = tid % 28;
        int lo = boxes[((size_t)b * 4 + (axis == 0 ? 0 : 1)) * NR + r];
        int hi = boxes[((size_t)b * 4 + (axis == 0 ? 2 : 3)) * NR + r];
        float L = (float)(hi - lo + 1);
        float g = __fsub_rn(__fdiv_rn(__fmul_rn((float)i + 0.5f, L), 28.0f), 0.5f);
        g = __fadd_rn(fminf(fmaxf(g, 0.0f), __fsub_rn(L, 1.0f)), (float)lo);
        int i0 = (int)floorf(g);
        float f = __fsub_rn(g, (float)i0);  // f computed BEFORE clamp (matches ref)
        i0 = min(i0, hi);
        int i1 = min(i0 + 1, hi);
        if (axis == 0) { sy0[i] = i0; sy1[i] = i1; sfy[i] = f; }
        else           { sx0[i] = i0; sx1[i] = i1; sfx[i] = f; }
    }
    __syncthreads();

    const float* fb = feats + (size_t)b * FEATC * HP * WP;
    float* ob = out + (((size_t)(b * NR + r) * FEATC + c0)) * (RX * RY);
    const int PQ = RX * RY / 4;            // 196 float4 groups per channel
    const int NE4 = CCH * PQ;              // 6272
    for (int e4 = tid; e4 < NE4; e4 += blockDim.x) {
        int c = e4 / PQ;
        int p4 = e4 % PQ;
        int oy = p4 / (RY / 4);
        int gx = (p4 % (RY / 4)) * 4;
        const float* fc = fb + (size_t)(c0 + c) * HP * WP;
        int y0 = sy0[oy], y1 = sy1[oy];
        float fy = sfy[oy];
        const float* row0 = fc + y0 * WP;
        const float* row1 = fc + y1 * WP;
        float tmp[4];
#pragma unroll
        for (int k = 0; k < 4; k++) {
            int ox = gx + k;
            int x0 = sx0[ox], x1 = sx1[ox];
            float fx = sfx[ox];
            float r0v = row0[x0] * (1.0f - fy) + row1[x0] * fy;
            float r1v = row0[x1] * (1.0f - fy) + row1[x1] * fy;
            tmp[k] = r0v * (1.0f - fx) + r1v * fx;
        }
        reinterpret_cast<float4*>(ob)[e4] =
            make_float4(tmp[0], tmp[1], tmp[2], tmp[3]);
    }
}

// ---------------------------------------------------------------------------
// IoU max / argmax vs 4356 anchors, with .at[g,best_g].max(0.6) update.
// PASSING VERSION — byte-identical to R14. div.full.f32 replicates XLA:GPU's
// approximate f32 division (the ~2-ulp op that decides the argmax winners).
// DO NOT TOUCH.
// ---------------------------------------------------------------------------
__device__ __forceinline__ float fdiv_full(float a, float b)
{
    float r;
    asm("div.full.f32 %0, %1, %2;" : "=f"(r) : "f"(a), "f"(b));
    return r;
}

__device__ __forceinline__ void anchor_coords(int a, const float* wh, const float* hh,
                                              float& ax1, float& ay1, float& ax2, float& ay2)
{
    int k = a / (HP * WP);
    int rem = a % (HP * WP);
    int iy = rem / WP, ix = rem % WP;
    float cx = fdiv_full((float)ix + 0.5f, (float)WP);
    float cy = fdiv_full((float)iy + 0.5f, (float)HP);
    ax1 = __fsub_rn(cx, wh[k]); ay1 = __fsub_rn(cy, hh[k]);
    ax2 = __fadd_rn(cx, wh[k]); ay2 = __fadd_rn(cy, hh[k]);
}

__device__ __forceinline__ float iou_one(float gx1, float gy1, float gx2, float gy2,
                                         float ax1, float ay1, float ax2, float ay2,
                                         float a_an)
{
    float ix1 = fmaxf(gx1, ax1), iy1 = fmaxf(gy1, ay1);
    float ix2 = fminf(gx2, ax2), iy2 = fminf(gy2, ay2);
    float cxw = fmaxf(__fsub_rn(ix2, ix1), 0.f);
    float cyw = fmaxf(__fsub_rn(iy2, iy1), 0.f);
    float inter = __fmul_rn(cxw, cyw);
    float a_gt = __fmul_rn(__fsub_rn(gx2, gx1), __fsub_rn(gy2, gy1));
    float denom = __fadd_rn(__fsub_rn(__fadd_rn(a_gt, a_an), inter), 1e-9f);
    return fdiv_full(inter, denom);
}

__global__ void iou_kernel(const float* __restrict__ gt_boxes,
                           float* __restrict__ iou_max_out,
                           float* __restrict__ iou_arg_out)
{
    int b = blockIdx.x;
    int tid = threadIdx.x;
    __shared__ float sgt[16];
    __shared__ float s_wh[NK], s_hh[NK];
    __shared__ float redv[256];
    __shared__ int   redi[256];
    __shared__ int   bestA[NG];

    if (tid < 16) sgt[tid] = gt_boxes[b * 16 + tid];
    if (tid < NK) {
        const double S[3] = {0.15, 0.45, 0.75};
        const double R[3] = {0.5, 1.0, 2.0};
        int si = tid / 3, ri = tid % 3;
        s_wh[tid] = (float)(S[si] * sqrt(R[ri]) * 0.5);
        s_hh[tid] = (float)(S[si] / sqrt(R[ri]) * 0.5);
    }
    __syncthreads();

    // phase 1: per-gt argmax over anchors (FIRST occurrence on ties)
    float bv[NG]; int bi[NG];
#pragma unroll
    for (int g = 0; g < NG; g++) { bv[g] = -1.0f; bi[g] = 0; }

    for (int a = tid; a < NANCH; a += 256) {
        float ax1, ay1, ax2, ay2;
        anchor_coords(a, s_wh, s_hh, ax1, ay1, ax2, ay2);
        float a_an = __fmul_rn(__fsub_rn(ax2, ax1), __fsub_rn(ay2, ay1));
#pragma unroll
        for (int g = 0; g < NG; g++) {
            float v = iou_one(sgt[g], sgt[4 + g], sgt[8 + g], sgt[12 + g],
                              ax1, ay1, ax2, ay2, a_an);
            if (v > bv[g]) { bv[g] = v; bi[g] = a; }   // strict > keeps FIRST
        }
    }
    for (int g = 0; g < NG; g++) {
        redv[tid] = bv[g]; redi[tid] = bi[g];
        __syncthreads();
        for (int s = 128; s > 0; s >>= 1) {
            if (tid < s) {
                float v2 = redv[tid + s]; int i2 = redi[tid + s];
                if (v2 > redv[tid] || (v2 == redv[tid] && i2 < redi[tid])) {
                    redv[tid] = v2; redi[tid] = i2;     // min index on ties
                }
            }
            __syncthreads();
        }
        if (tid == 0) bestA[g] = redi[0];
        __syncthreads();
    }

    // phase 2: per-anchor max/argmax over gts with the 0.6 scatter applied
    for (int a = tid; a < NANCH; a += 256) {
        float ax1, ay1, ax2, ay2;
        anchor_coords(a, s_wh, s_hh, ax1, ay1, ax2, ay2);
        float a_an = __fmul_rn(__fsub_rn(ax2, ax1), __fsub_rn(ay2, ay1));
        float m = -1.0f; int am = 0;
#pragma unroll
        for (int g = 0; g < NG; g++) {
            float v = iou_one(sgt[g], sgt[4 + g], sgt[8 + g], sgt[12 + g],
                              ax1, ay1, ax2, ay2, a_an);
            if (a == bestA[g]) v = fmaxf(v, 0.6f);
            if (v > m) { m = v; am = g; }               // strict > keeps FIRST
        }
        iou_max_out[b * NANCH + a] = m;
        iou_arg_out[b * NANCH + a] = (float)am;
    }
}

// ---------------------------------------------------------------------------
// Launch
// ---------------------------------------------------------------------------
static inline int cdiv(int a, int b) { return (a + b - 1) / b; }

extern "C" void kernel_launch(void* const* d_in, const int* in_sizes, int n_in,
                              void* d_out, int out_size)
{
    const float* x     = (const float*)d_in[0];
    const int*   boxes = (const int*)  d_in[1];
    const float* gt    = (const float*)d_in[2];
    const float* fw[8]; const float* fb[8];
    for (int i = 0; i < 8; i++) {
        fw[i] = (const float*)d_in[3 + 2 * i];
        fb[i] = (const float*)d_in[4 + 2 * i];
    }
    const float* rw0 = (const float*)d_in[19];
    const float* rb0 = (const float*)d_in[20];
    const float* rw1 = (const float*)d_in[21];
    const float* rb1 = (const float*)d_in[22];
    float* out = (float*)d_out;

    float *b0, *b1, *b2;
    cudaGetSymbolAddress((void**)&b0, g_buf0);
    cudaGetSymbolAddress((void**)&b1, g_buf1);
    cudaGetSymbolAddress((void**)&b2, g_buf2);

    float* feats = out + OFF_FEATS;
    float* conf  = out + OFF_CONF;
    float* diffs = out + OFF_DIFFS;
    float* reg   = out + OFF_REG;
    float* ioumx = out + OFF_IOUMAX;
    float* iouag = out + OFF_IOUARG;

    // conv0: 1->16, 112->110, pad0.  tiles 7x7=49, oc groups 16/8=2
    conv3x3_v2<16,16,8,1,1,0,true><<<dim3(49, 2, BATCH), 256>>>(
        x, fw[0], fb[0], b0, 1, 16, 112, 112, 110, 110);
    // conv1: 16->16 @110, pad1
    conv3x3_v2<16,16,8,4,1,1,true><<<dim3(49, 2, BATCH), 256>>>(
        b0, fw[1], fb[1], b1, 16, 16, 110, 110, 110, 110);
    // pool1: 110->55
    {
        int n = BATCH * 16 * 55 * 55;
        maxpool_kernel<<<cdiv(n, 256), 256>>>(b1, b2, 110, 110, 55, 55, n);
    }
    // conv2: 16->32, 55->53, pad0.  tiles 4x4=16, groups 32/8=4
    conv3x3_v2<16,16,8,4,1,0,true><<<dim3(16, 4, BATCH), 256>>>(
        b2, fw[2], fb[2], b0, 16, 32, 55, 55, 53, 53);
    // conv3: 32->32 @53, pad1
    conv3x3_v2<16,16,8,4,1,1,true><<<dim3(16, 4, BATCH), 256>>>(
        b0, fw[3], fb[3], b1, 32, 32, 53, 53, 53, 53);
    // pool2: 53->26
    {
        int n = BATCH * 32 * 26 * 26;
        maxpool_kernel<<<cdiv(n, 256), 256>>>(b1, b2, 53, 53, 26, 26, n);
    }
    // conv4: 32->64, 26->24, pad0.  tiles 1x2=2 (12x24), groups 64/4=16
    conv3x3_v2<12,24,4,8,2,0,true><<<dim3(2, 16, BATCH), 256>>>(
        b2, fw[4], fb[4], b0, 32, 64, 26, 26, 24, 24);
    // conv5: 64->64 @24, pad1
    conv3x3_v2<12,24,4,8,2,1,true><<<dim3(2, 16, BATCH), 256>>>(
        b0, fw[5], fb[5], b1, 64, 64, 24, 24, 24, 24);
    // conv6: 64->128, 24->22, pad0.  tiles 1x2=2 (11x22), groups 128/4=32
    conv3x3_v2<11,22,4,8,1,0,true><<<dim3(2, 32, BATCH), 256>>>(
        b1, fw[6], fb[6], b0, 64, 128, 24, 24, 22, 22);
    // conv7: 128->128 @22, pad1 -> feats
    conv3x3_v2<11,22,4,8,1,1,true><<<dim3(2, 32, BATCH), 256>>>(
        b0, fw[7], fb[7], feats, 128, 128, 22, 22, 22, 22);
    // rw0: 128->256 @22, pad1, relu.  groups 256/4=64
    conv3x3_v2<11,22,4,8,1,1,true><<<dim3(2, 64, BATCH), 256>>>(
        feats, rw0, rb0, b2, 128, 256, 22, 22, 22, 22);
    // rw1 1x1 head -> conf + diffs (fused sigmoid/split)
    {
        int total = BATCH * 45 * HP * WP;
        head1x1_kernel<<<cdiv(total, 256), 256>>>(b2, rw1, rb1, conf, diffs);
    }
    // regions: bilinear crops
    regions_kernel<<<dim3(FEATC / 32, NR, BATCH), 256>>>(feats, boxes, reg);
    // iou
    iou_kernel<<<BATCH, 256>>>(gt, ioumx, iouag);
}